// round 14
// baseline (speedup 1.0000x reference)
#include <cuda_runtime.h>
#include <cuda_bf16.h>

#define TLEN 2048
#define H 20
typedef unsigned long long ull;

// ---- packed f32x2 helpers ----
__device__ __forceinline__ ull pk(float lo, float hi) {
    ull r; asm("mov.b64 %0, {%1, %2};" : "=l"(r) : "f"(lo), "f"(hi)); return r;
}
__device__ __forceinline__ float2 upk(ull v) {
    float2 f; asm("mov.b64 {%0, %1}, %2;" : "=f"(f.x), "=f"(f.y) : "l"(v)); return f;
}
__device__ __forceinline__ ull fma2(ull a, ull b, ull c) {
    ull d; asm("fma.rn.f32x2 %0, %1, %2, %3;" : "=l"(d) : "l"(a), "l"(b), "l"(c)); return d;
}
__device__ __forceinline__ ull mul2(ull a, ull b) {
    ull d; asm("mul.rn.f32x2 %0, %1, %2;" : "=l"(d) : "l"(a), "l"(b)); return d;
}
__device__ __forceinline__ ull add2(ull a, ull b) {
    ull d; asm("add.rn.f32x2 %0, %1, %2;" : "=l"(d) : "l"(a), "l"(b)); return d;
}
__device__ __forceinline__ float tanh_hw(float z) {
    float r; asm("tanh.approx.f32 %0, %1;" : "=f"(r) : "f"(z)); return r;
}
__device__ __forceinline__ float sigmoid1(float z) {
    float e; asm("ex2.approx.f32 %0, %1;" : "=f"(e) : "f"(z * -1.4426950408889634f));
    float r; asm("rcp.approx.f32 %0, %1;" : "=f"(r) : "f"(e + 1.0f));
    return r;
}

// Global K-pair permutation (dot order-free):
//   g in [0,8): rows (5*(g>>1) + 2*(g&1), +1) -> thread q OWNS pairs 2q, 2q+1
//               (= rows 5q..5q+3 = its own m[0..3])
//   g = 8: rows (4,9)   g = 9: rows (14,19)   (straddle pairs; m[4] halves)
__device__ __forceinline__ int pairA(int g) {
    if (g == 8) return 4;
    if (g == 9) return 14;
    return 5 * (g >> 1) + 2 * (g & 1);
}
__device__ __forceinline__ int pairB(int g) {
    if (g == 8) return 9;
    if (g == 9) return 19;
    return 5 * (g >> 1) + 2 * (g & 1) + 1;
}

// R14 = R8 shape (2 streams, 1024 blocks, weights fully register-resident,
// single wave) + Q-ROTATED pair layout to shorten the recurrence spine:
// thread q keeps local slot j = global pair (2q+j)%10, so slots 0,1 are its
// OWN rows (m[0..3]). Own pairs are rebuilt locally after tanh (no smem
// round-trip, -4 LDS.64/substep) and both dot chains START on them, hiding
// the 29-cyc LDS latency of the 8 foreign pairs behind ~3 fma2 of slack.
// Input projection folded in as virtual pair (wih,pre).(x,1).
__global__ void __launch_bounds__(32) rnn_kernel(
    const float* __restrict__ x, const float* __restrict__ W_ih,
    const float* __restrict__ W_hh, const float* __restrict__ b_ih,
    const float* __restrict__ b_hh, const float* __restrict__ W_fc,
    const float* __restrict__ b_fc, float* __restrict__ out)
{
    __shared__ float sW[H][H];
    __shared__ ull hbuf[2][2][10][8];     // [buf][stream][global pair][batch8]
    __shared__ float sWih[H], sPre[H], sWfc[H];
    __shared__ float sBfc;

    const int tid = threadIdx.x;
    for (int i = tid; i < H * H; i += 32) sW[i / H][i % H] = W_hh[i];
    if (tid < H) {
        sWih[tid] = W_ih[tid];
        sPre[tid] = b_ih[tid] + b_hh[tid];
        sWfc[tid] = W_fc[tid];
    }
    if (tid == 0) sBfc = b_fc[0];
    __syncthreads();

    const int q  = tid & 3;
    const int b8 = tid >> 2;
    const int batchA = blockIdx.x * 16 + b8;
    const int batchB = batchA + 8;

    // q-rotated register weights: local slot j <-> global pair (2q+j)%10
    ull wr[5][10], wihpre[5];
    int gidx[8];                           // global pair for local slots 2..9
    #pragma unroll
    for (int j = 0; j < 8; j++) gidx[j] = (2 * q + 2 + j) % 10;
    #pragma unroll
    for (int i = 0; i < 5; i++) {
        const int r = 5 * q + i;
        #pragma unroll
        for (int j = 0; j < 10; j++) {
            const int g = (2 * q + j) % 10;
            wr[i][j] = pk(sW[r][pairA(g)], sW[r][pairB(g)]);
        }
        wihpre[i] = pk(sWih[r], sPre[r]);
    }

    ull hqA[10], hqB[10];
    #pragma unroll
    for (int j = 0; j < 10; j++) { hqA[j] = 0ull; hqB[j] = 0ull; }

    const float* xpA = x + (size_t)batchA * TLEN;
    const float* xpB = x + (size_t)batchB * TLEN;

    for (int t = 0; t < TLEN; t += 4) {
        const float4 xva = *(const float4*)(xpA + t);
        const float4 xvb = *(const float4*)(xpB + t);
        const float xa[4] = {xva.x, xva.y, xva.z, xva.w};
        const float xb[4] = {xvb.x, xvb.y, xvb.z, xvb.w};

        #pragma unroll
        for (int s = 0; s < 4; s++) {
            const int buf = s & 1;
            const ull hxA = pk(xa[s], 1.0f);
            const ull hxB = pk(xb[s], 1.0f);
            float ma[5], mb[5];
            #pragma unroll
            for (int i = 0; i < 5; i++) {
                // chains start on LOCAL slots 0,1 (own rows, zero-latency);
                // foreign (LDS-sourced) slots come later in the chain.
                ull aL = mul2(wr[i][0], hqA[0]);     // L: 0,2,4,6,8
                ull aH = mul2(wihpre[i], hxA);       // H: virt,1,3,5,7,9
                ull bL = mul2(wr[i][0], hqB[0]);
                ull bH = mul2(wihpre[i], hxB);
                aH = fma2(wr[i][1], hqA[1], aH);
                bH = fma2(wr[i][1], hqB[1], bH);
                #pragma unroll
                for (int j = 1; j < 5; j++) {
                    aL = fma2(wr[i][2 * j],     hqA[2 * j],     aL);
                    aH = fma2(wr[i][2 * j + 1], hqA[2 * j + 1], aH);
                    bL = fma2(wr[i][2 * j],     hqB[2 * j],     bL);
                    bH = fma2(wr[i][2 * j + 1], hqB[2 * j + 1], bH);
                }
                float2 fa = upk(add2(aL, aH));
                float2 fb = upk(add2(bL, bH));
                ma[i] = tanh_hw(fa.x + fa.y);
                mb[i] = tanh_hw(fb.x + fb.y);
            }
            // exchange: write own pairs (global slots) + straddle scalar
            hbuf[buf][0][2 * q][b8]     = pk(ma[0], ma[1]);
            hbuf[buf][0][2 * q + 1][b8] = pk(ma[2], ma[3]);
            ((float*)&hbuf[buf][0][8 + (q >> 1)][b8])[q & 1] = ma[4];
            hbuf[buf][1][2 * q][b8]     = pk(mb[0], mb[1]);
            hbuf[buf][1][2 * q + 1][b8] = pk(mb[2], mb[3]);
            ((float*)&hbuf[buf][1][8 + (q >> 1)][b8])[q & 1] = mb[4];
            __syncwarp();
            // own pairs: rebuilt locally, NO smem round-trip
            hqA[0] = pk(ma[0], ma[1]);  hqA[1] = pk(ma[2], ma[3]);
            hqB[0] = pk(mb[0], mb[1]);  hqB[1] = pk(mb[2], mb[3]);
            // foreign pairs: 8 LDS.64 per stream, rotated indices
            #pragma unroll
            for (int j = 0; j < 8; j++) {
                hqA[2 + j] = hbuf[buf][0][gidx[j]][b8];
                hqB[2 + j] = hbuf[buf][1][gidx[j]][b8];
            }
        }
    }

    if (q == 0) {   // rotation is identity for q=0: hq[j] = global pair j
        ull accA = pk(sBfc, 0.0f), accB = pk(sBfc, 0.0f);
        #pragma unroll
        for (int j = 0; j < 10; j++) {
            ull wf = pk(sWfc[pairA(j)], sWfc[pairB(j)]);
            accA = fma2(hqA[j], wf, accA);
            accB = fma2(hqB[j], wf, accB);
        }
        float2 fa = upk(accA), fb = upk(accB);
        out[batchA] = sigmoid1(fa.x + fa.y);
        out[batchB] = sigmoid1(fb.x + fb.y);
    }
}

extern "C" void kernel_launch(void* const* d_in, const int* in_sizes, int n_in,
                              void* d_out, int out_size) {
    const float* x    = (const float*)d_in[0];
    const float* W_ih = (const float*)d_in[1];
    const float* W_hh = (const float*)d_in[2];
    const float* b_ih = (const float*)d_in[3];
    const float* b_hh = (const float*)d_in[4];
    const float* W_fc = (const float*)d_in[5];
    const float* b_fc = (const float*)d_in[6];
    float* out = (float*)d_out;

    const int B = in_sizes[0] / TLEN;   // 16384
    rnn_kernel<<<B / 16, 32>>>(x, W_ih, W_hh, b_ih, b_hh, W_fc, b_fc, out);
}

// round 16
// speedup vs baseline: 2.3201x; 2.3201x over previous
#include <cuda_runtime.h>
#include <cuda_bf16.h>
#include <cstdint>

#define TLEN 2048
#define H 20

__device__ __forceinline__ float tanh_hw(float z) {
    float r; asm("tanh.approx.f32 %0, %1;" : "=f"(r) : "f"(z)); return r;
}
__device__ __forceinline__ float sigmoid1(float z) {
    float e; asm("ex2.approx.f32 %0, %1;" : "=f"(e) : "f"(z * -1.4426950408889634f));
    float r; asm("rcp.approx.f32 %0, %1;" : "=f"(r) : "f"(e + 1.0f));
    return r;
}
// pack two f32 into bf16x2: lower half = lo, upper half = hi
__device__ __forceinline__ uint32_t pkbf(float lo, float hi) {
    uint32_t w; asm("cvt.rn.bf16x2.f32 %0, %1, %2;" : "=r"(w) : "f"(hi), "f"(lo)); return w;
}
// D += A(16x16 bf16) * B(16x8 bf16, col-major) ; baseline PTX (sm_80+), no 'a' target needed
__device__ __forceinline__ void mma16816(float* c, const uint32_t* a, const uint32_t* b) {
    asm volatile(
        "mma.sync.aligned.m16n8k16.row.col.f32.bf16.bf16.f32 "
        "{%0,%1,%2,%3}, {%4,%5,%6,%7}, {%8,%9}, {%0,%1,%2,%3};"
        : "+f"(c[0]), "+f"(c[1]), "+f"(c[2]), "+f"(c[3])
        : "r"(a[0]), "r"(a[1]), "r"(a[2]), "r"(a[3]), "r"(b[0]), "r"(b[1]));
}

// One warp = 2 independent batch-tiles of 16 (32 batches). Recurrence as MMA:
//   D[16,24] = h[16,32] * W^T   (3 n-tiles x 2 k-tiles, bf16, W split hi+lo)
// Fragment closure: D elements (lane g=l>>2,t=l%4: rows {g,g+8} x cols {2t,2t+1})
// map EXACTLY onto the A-fragment slots, so D -> tanh -> cvt.bf16x2 -> A needs
// no shuffles/smem/syncs. C-operand carries the x-projection. FC head uses the
// f32 tanh outputs (bf16 quantization only enters via the contracting
// recurrence; R8 measured per-step noise attenuation ~1e-3).
// Grid 512 x 32: 3.46 warps/SM, single wave, zero smem.
__global__ void __launch_bounds__(32) rnn_tc(
    const float* __restrict__ x,      // [B, TLEN]
    const float* __restrict__ W_ih,   // [H]
    const float* __restrict__ W_hh,   // [H, H]
    const float* __restrict__ b_ih,   // [H]
    const float* __restrict__ b_hh,   // [H]
    const float* __restrict__ W_fc,   // [H]
    const float* __restrict__ b_fc,   // [1]
    float* __restrict__ out)          // [B]
{
    const int lane = threadIdx.x & 31;
    const int g  = lane >> 2;          // fragment group row 0..7
    const int tg = lane & 3;           // thread-in-group 0..3
    const int base = blockIdx.x * 32;  // 32 batches per warp

    // ---- B fragments: [ktile][ntile][hi/lo][2 regs], shared by both tiles ----
    // b0 = {B[2t][g], B[2t+1][g]}, b1 = {B[2t+8][g], B[2t+9][g]}; B[k][n]=W[8j+g][k]
    uint32_t Bf[2][3][2][2];
    #pragma unroll
    for (int kt = 0; kt < 2; kt++) {
        #pragma unroll
        for (int j = 0; j < 3; j++) {
            const int r = 8 * j + g;
            const int k0 = 16 * kt + 2 * tg;
            float w[4], whi[4], wlo[4];
            #pragma unroll
            for (int e = 0; e < 4; e++) {
                const int k = k0 + (e >> 1) * 8 + (e & 1);
                w[e] = (r < H && k < H) ? W_hh[r * H + k] : 0.0f;
                __nv_bfloat16 hb = __float2bfloat16(w[e]);
                whi[e] = __bfloat162float(hb);
                wlo[e] = w[e] - whi[e];
            }
            Bf[kt][j][0][0] = pkbf(whi[0], whi[1]);
            Bf[kt][j][0][1] = pkbf(whi[2], whi[3]);
            Bf[kt][j][1][0] = pkbf(wlo[0], wlo[1]);
            Bf[kt][j][1][1] = pkbf(wlo[2], wlo[3]);
        }
    }

    // ---- per-lane column constants (cols 8j + 2t + i) ----
    float wihc[3][2], prec[3][2], wfcc[3][2];
    #pragma unroll
    for (int j = 0; j < 3; j++)
        #pragma unroll
        for (int i = 0; i < 2; i++) {
            const int c = 8 * j + 2 * tg + i;
            const bool v = (c < H);
            wihc[j][i] = v ? W_ih[c] : 0.0f;
            prec[j][i] = v ? (b_ih[c] + b_hh[c]) : 0.0f;
            wfcc[j][i] = v ? W_fc[c] : 0.0f;
        }
    const float bfc = b_fc[0];

    // ---- x streams: rows g, g+8 of each tile ----
    const float* xp0 = x + (size_t)(base + g) * TLEN;        // tile0 row g
    const float* xp1 = x + (size_t)(base + g + 8) * TLEN;    // tile0 row g+8
    const float* xp2 = x + (size_t)(base + 16 + g) * TLEN;   // tile1 row g
    const float* xp3 = x + (size_t)(base + 24 + g) * TLEN;   // tile1 row g+8

    uint32_t A0[2][4], A1[2][4];       // [tile][reg], k-tile0 / k-tile1
    #pragma unroll
    for (int r = 0; r < 4; r++) { A0[0][r] = A0[1][r] = A1[0][r] = A1[1][r] = 0u; }
    float th0[12], th1[12];            // f32 tanh outputs (final step feeds FC)

    for (int t = 0; t < TLEN; t += 4) {
        const float4 v0 = *(const float4*)(xp0 + t);
        const float4 v1 = *(const float4*)(xp1 + t);
        const float4 v2 = *(const float4*)(xp2 + t);
        const float4 v3 = *(const float4*)(xp3 + t);
        const float xs0[4] = {v0.x, v0.y, v0.z, v0.w};
        const float xs1[4] = {v1.x, v1.y, v1.z, v1.w};
        const float xs2[4] = {v2.x, v2.y, v2.z, v2.w};
        const float xs3[4] = {v3.x, v3.y, v3.z, v3.w};

        #pragma unroll
        for (int s = 0; s < 4; s++) {
            float c0[3][4], c1[3][4];
            #pragma unroll
            for (int j = 0; j < 3; j++) {
                c0[j][0] = fmaf(xs0[s], wihc[j][0], prec[j][0]);
                c0[j][1] = fmaf(xs0[s], wihc[j][1], prec[j][1]);
                c0[j][2] = fmaf(xs1[s], wihc[j][0], prec[j][0]);
                c0[j][3] = fmaf(xs1[s], wihc[j][1], prec[j][1]);
                c1[j][0] = fmaf(xs2[s], wihc[j][0], prec[j][0]);
                c1[j][1] = fmaf(xs2[s], wihc[j][1], prec[j][1]);
                c1[j][2] = fmaf(xs3[s], wihc[j][0], prec[j][0]);
                c1[j][3] = fmaf(xs3[s], wihc[j][1], prec[j][1]);
            }
            // 12 MMAs per tile: 3 n-chains x (hi-k0, hi-k1, lo-k0, lo-k1)
            #pragma unroll
            for (int j = 0; j < 3; j++) {
                mma16816(c0[j], A0[0], Bf[0][j][0]);
                mma16816(c1[j], A1[0], Bf[0][j][0]);
                mma16816(c0[j], A0[1], Bf[1][j][0]);
                mma16816(c1[j], A1[1], Bf[1][j][0]);
                mma16816(c0[j], A0[0], Bf[0][j][1]);
                mma16816(c1[j], A1[0], Bf[0][j][1]);
                mma16816(c0[j], A0[1], Bf[1][j][1]);
                mma16816(c1[j], A1[1], Bf[1][j][1]);
            }
            #pragma unroll
            for (int j = 0; j < 3; j++)
                #pragma unroll
                for (int i = 0; i < 4; i++) {
                    th0[j * 4 + i] = tanh_hw(c0[j][i]);
                    th1[j * 4 + i] = tanh_hw(c1[j][i]);
                }
            // D -> A (fragment-closed): tile j=0 -> a0,a1; j=1 -> a2,a3; j=2 -> k-tile1 a0,a1
            A0[0][0] = pkbf(th0[0], th0[1]);   A0[0][1] = pkbf(th0[2],  th0[3]);
            A0[0][2] = pkbf(th0[4], th0[5]);   A0[0][3] = pkbf(th0[6],  th0[7]);
            A0[1][0] = pkbf(th0[8], th0[9]);   A0[1][1] = pkbf(th0[10], th0[11]);
            A0[1][2] = 0u;                     A0[1][3] = 0u;
            A1[0][0] = pkbf(th1[0], th1[1]);   A1[0][1] = pkbf(th1[2],  th1[3]);
            A1[0][2] = pkbf(th1[4], th1[5]);   A1[0][3] = pkbf(th1[6],  th1[7]);
            A1[1][0] = pkbf(th1[8], th1[9]);   A1[1][1] = pkbf(th1[10], th1[11]);
            A1[1][2] = 0u;                     A1[1][3] = 0u;
        }
    }

    // ---- FC head + sigmoid from f32 tanh outputs ----
    float pA0 = 0.f, pB0 = 0.f, pA1 = 0.f, pB1 = 0.f;
    #pragma unroll
    for (int j = 0; j < 3; j++)
        #pragma unroll
        for (int i = 0; i < 2; i++) {
            pA0 = fmaf(th0[j * 4 + i],     wfcc[j][i], pA0);   // row g
            pB0 = fmaf(th0[j * 4 + 2 + i], wfcc[j][i], pB0);   // row g+8
            pA1 = fmaf(th1[j * 4 + i],     wfcc[j][i], pA1);
            pB1 = fmaf(th1[j * 4 + 2 + i], wfcc[j][i], pB1);
        }
    // reduce across the 4 lanes of each fragment row group
    #pragma unroll
    for (int d = 1; d < 4; d <<= 1) {
        pA0 += __shfl_xor_sync(0xffffffffu, pA0, d, 32);
        pB0 += __shfl_xor_sync(0xffffffffu, pB0, d, 32);
        pA1 += __shfl_xor_sync(0xffffffffu, pA1, d, 32);
        pB1 += __shfl_xor_sync(0xffffffffu, pB1, d, 32);
    }
    if (tg == 0) {
        out[base + g]      = sigmoid1(pA0 + bfc);
        out[base + g + 8]  = sigmoid1(pB0 + bfc);
        out[base + 16 + g] = sigmoid1(pA1 + bfc);
        out[base + 24 + g] = sigmoid1(pB1 + bfc);
    }
}

extern "C" void kernel_launch(void* const* d_in, const int* in_sizes, int n_in,
                              void* d_out, int out_size) {
    const float* x    = (const float*)d_in[0];
    const float* W_ih = (const float*)d_in[1];
    const float* W_hh = (const float*)d_in[2];
    const float* b_ih = (const float*)d_in[3];
    const float* b_hh = (const float*)d_in[4];
    const float* W_fc = (const float*)d_in[5];
    const float* b_fc = (const float*)d_in[6];
    float* out = (float*)d_out;

    const int B = in_sizes[0] / TLEN;   // 16384
    const int blocks = B / 32;          // 512 warps, 2 MMA tiles each
    rnn_tc<<<blocks, 32>>>(x, W_ih, W_hh, b_ih, b_hh, W_fc, b_fc, out);
}